// round 4
// baseline (speedup 1.0000x reference)
#include <cuda_runtime.h>
#include <cstdint>

// ---------------------------------------------------------------------------
// Fused AUGRU cell via legacy mma.sync TF32 (PTX target sm_100-safe).
//   B=16384, D=H=512. CTA tile M=128 x N=64; 256 thr = 8 warps (4 m x 2 n).
//   Warp tile 32x32. K chunk = 32, double-buffered cp.async.
//   Phase 0 (chunks 0-15):  A=x,   Bs={W_u,W_r,W_h} -> Zu,Zr,Zx
//   Phase 1 (chunks 16-31): A=hid, Bs={U_u,U_r,U_h} -> Zu,Zr,S
//   Epilogue: u=att*sig(Zu+bu), r=sig(Zr+br), hh=tanh(Zx+r*S+bh),
//             out=(1-u)*h + u*hh.
// ---------------------------------------------------------------------------

#define TB 256

// smem (floats): A [128][36], B_w [32][72] x3, double buffered.
#define A_STRIDE   36
#define B_STRIDE   72
#define A_FLOATS   (128 * A_STRIDE)                 // 4608
#define B_FLOATS   (32 * B_STRIDE)                  // 2304
#define BUF_FLOATS (A_FLOATS + 3 * B_FLOATS)        // 11520
#define AOFF(b)    ((b) * BUF_FLOATS)
#define BOFF(b, w) ((b) * BUF_FLOATS + A_FLOATS + (w) * B_FLOATS)
#define SMEM_BYTES (2 * BUF_FLOATS * 4)             // 92160

static __device__ __forceinline__ uint32_t smem_u32(const void* p) {
    uint32_t a;
    asm("{ .reg .u64 t; cvta.to.shared.u64 t, %1; cvt.u32.u64 %0, t; }"
        : "=r"(a) : "l"(p));
    return a;
}

static __device__ __forceinline__ void cp16(uint32_t dst, const void* src) {
    asm volatile("cp.async.cg.shared.global [%0], [%1], 16;"
                 :: "r"(dst), "l"(src) : "memory");
}
static __device__ __forceinline__ void cp_commit() {
    asm volatile("cp.async.commit_group;" ::: "memory");
}
static __device__ __forceinline__ void cp_wait1() {
    asm volatile("cp.async.wait_group 1;" ::: "memory");
}
static __device__ __forceinline__ void cp_wait0() {
    asm volatile("cp.async.wait_group 0;" ::: "memory");
}

static __device__ __forceinline__ uint32_t to_tf32(float f) {
    uint32_t r;
    asm("cvt.rna.tf32.f32 %0, %1;" : "=r"(r) : "f"(f));
    return r;
}

static __device__ __forceinline__ void mma8(float* d, const uint32_t* a,
                                            const uint32_t* b) {
    asm volatile(
        "mma.sync.aligned.m16n8k8.row.col.f32.tf32.tf32.f32 "
        "{%0,%1,%2,%3}, {%4,%5,%6,%7}, {%8,%9}, {%0,%1,%2,%3};"
        : "+f"(d[0]), "+f"(d[1]), "+f"(d[2]), "+f"(d[3])
        : "r"(a[0]), "r"(a[1]), "r"(a[2]), "r"(a[3]), "r"(b[0]), "r"(b[1]));
}

static __device__ __forceinline__ float sigmoidf_fast(float z) {
    return 1.0f / (1.0f + __expf(-z));
}
static __device__ __forceinline__ float tanhf_fast(float z) {
    return 1.0f - 2.0f / (1.0f + __expf(2.0f * z));
}

__global__ void __launch_bounds__(TB, 1)
augru_kernel(const float* __restrict__ x,  const float* __restrict__ att,
             const float* __restrict__ hid,
             const float* __restrict__ Wu, const float* __restrict__ Uu,
             const float* __restrict__ b_u,
             const float* __restrict__ Wr, const float* __restrict__ Ur,
             const float* __restrict__ b_r,
             const float* __restrict__ Wh, const float* __restrict__ Uh,
             const float* __restrict__ b_h,
             float* __restrict__ out)
{
    extern __shared__ float sm[];
    const uint32_t sb = smem_u32(sm);
    const int tid  = threadIdx.x;
    const int lane = tid & 31;
    const int wid  = tid >> 5;
    const int g = lane >> 2;       // group id (0..7)
    const int t = lane & 3;        // thread-in-group (0..3)
    const int wm = wid & 3;        // warp m index (0..3) -> 32 rows
    const int wn = wid >> 2;       // warp n index (0..1) -> 32 cols
    const int m0 = (int)blockIdx.y << 7;
    const int n0 = (int)blockIdx.x << 6;

    // accumulators: [mt][nt][e], e: (row g / g+8) x (col 2t / 2t+1)
    float accU[2][4][4], accR[2][4][4], accX[2][4][4], accS[2][4][4];
    #pragma unroll
    for (int mt = 0; mt < 2; mt++)
        #pragma unroll
        for (int nt = 0; nt < 4; nt++)
            #pragma unroll
            for (int e = 0; e < 4; e++) {
                accU[mt][nt][e] = 0.f; accR[mt][nt][e] = 0.f;
                accX[mt][nt][e] = 0.f; accS[mt][nt][e] = 0.f;
            }

    // ---- chunk loader: issue cp.async for chunk c into buffer b ------------
    auto load_chunk = [&](int c, int b) {
        const int ph = (c >= 16);
        const int k0 = (c & 15) << 5;
        const float* Ap = ph ? hid : x;
        // A: 128 rows x 32 floats
        #pragma unroll
        for (int i = 0; i < 4; i++) {
            const int idx = tid + TB * i;
            const int row = idx >> 3;
            const int c4  = idx & 7;
            cp16(sb + (AOFF(b) + row * A_STRIDE + c4 * 4) * 4,
                 Ap + (size_t)(m0 + row) * 512 + k0 + c4 * 4);
        }
        // B: 3 weights, 32 rows x 64 floats each
        #pragma unroll
        for (int w = 0; w < 3; w++) {
            const float* Wp = ph ? (w == 0 ? Uu : (w == 1 ? Ur : Uh))
                                 : (w == 0 ? Wu : (w == 1 ? Wr : Wh));
            #pragma unroll
            for (int i = 0; i < 2; i++) {
                const int idx = tid + TB * i;
                const int kr = idx >> 4;
                const int n4 = idx & 15;
                cp16(sb + (BOFF(b, w) + kr * B_STRIDE + n4 * 4) * 4,
                     Wp + (size_t)(k0 + kr) * 512 + n0 + n4 * 4);
            }
        }
        cp_commit();
    };

    load_chunk(0, 0);

    for (int c = 0; c < 32; c++) {
        const int b = c & 1;
        if (c + 1 < 32) { load_chunk(c + 1, (c + 1) & 1); cp_wait1(); }
        else            { cp_wait0(); }
        __syncthreads();

        const float* As = sm + AOFF(b) + (wm * 32) * A_STRIDE;
        const int ph = (c >= 16);

        #pragma unroll
        for (int ks = 0; ks < 4; ks++) {
            const int kc = 8 * ks + t;
            // A fragments (conflict-free: bank = 4g + t)
            uint32_t a[2][4];
            #pragma unroll
            for (int mt = 0; mt < 2; mt++) {
                const float* Ar = As + (mt * 16 + g) * A_STRIDE;
                a[mt][0] = to_tf32(Ar[kc]);
                a[mt][1] = to_tf32(Ar[8 * A_STRIDE + kc]);
                a[mt][2] = to_tf32(Ar[kc + 4]);
                a[mt][3] = to_tf32(Ar[8 * A_STRIDE + kc + 4]);
            }
            // B fragments (conflict-free: bank = 8t + g)
            uint32_t bb[3][4][2];
            #pragma unroll
            for (int w = 0; w < 3; w++) {
                const float* Bs = sm + BOFF(b, w) + kc * B_STRIDE + wn * 32 + g;
                #pragma unroll
                for (int nt = 0; nt < 4; nt++) {
                    bb[w][nt][0] = to_tf32(Bs[8 * nt]);
                    bb[w][nt][1] = to_tf32(Bs[4 * B_STRIDE + 8 * nt]);
                }
            }
            #pragma unroll
            for (int mt = 0; mt < 2; mt++)
                #pragma unroll
                for (int nt = 0; nt < 4; nt++) {
                    mma8(accU[mt][nt], a[mt], bb[0][nt]);
                    mma8(accR[mt][nt], a[mt], bb[1][nt]);
                    if (!ph) mma8(accX[mt][nt], a[mt], bb[2][nt]);
                    else     mma8(accS[mt][nt], a[mt], bb[2][nt]);
                }
        }
        __syncthreads();
    }

    // ---- epilogue: gates + blend, float2 stores ----------------------------
    #pragma unroll
    for (int mt = 0; mt < 2; mt++) {
        #pragma unroll
        for (int er = 0; er < 2; er++) {
            const int m = m0 + wm * 32 + mt * 16 + g + er * 8;
            const float am = __ldg(att + m);
            const float* hrow = hid + (size_t)m * 512;
            float*       orow = out + (size_t)m * 512;
            #pragma unroll
            for (int nt = 0; nt < 4; nt++) {
                const int col = n0 + wn * 32 + nt * 8 + t * 2;
                const float2 h2  = __ldg((const float2*)(hrow + col));
                const float2 bu2 = __ldg((const float2*)(b_u + col));
                const float2 br2 = __ldg((const float2*)(b_r + col));
                const float2 bh2 = __ldg((const float2*)(b_h + col));
                float o[2];
                #pragma unroll
                for (int ec = 0; ec < 2; ec++) {
                    const int e = er * 2 + ec;
                    const float zu = accU[mt][nt][e] + (ec ? bu2.y : bu2.x);
                    const float zr = accR[mt][nt][e] + (ec ? br2.y : br2.x);
                    const float u  = am * sigmoidf_fast(zu);
                    const float r  = sigmoidf_fast(zr);
                    const float hh = tanhf_fast(accX[mt][nt][e] +
                                                r * accS[mt][nt][e] +
                                                (ec ? bh2.y : bh2.x));
                    const float hv = ec ? h2.y : h2.x;
                    o[ec] = (1.0f - u) * hv + u * hh;
                }
                *(float2*)(orow + col) = make_float2(o[0], o[1]);
            }
        }
    }
}

extern "C" void kernel_launch(void* const* d_in, const int* in_sizes, int n_in,
                              void* d_out, int out_size) {
    (void)in_sizes; (void)n_in; (void)out_size;
    const float* x   = (const float*)d_in[0];
    const float* att = (const float*)d_in[1];
    const float* hid = (const float*)d_in[2];
    const float* Wu  = (const float*)d_in[3];
    const float* Uu  = (const float*)d_in[4];
    const float* b_u = (const float*)d_in[5];
    const float* Wr  = (const float*)d_in[6];
    const float* Ur  = (const float*)d_in[7];
    const float* b_r = (const float*)d_in[8];
    const float* Wh  = (const float*)d_in[9];
    const float* Uh  = (const float*)d_in[10];
    const float* b_h = (const float*)d_in[11];
    float* out = (float*)d_out;

    cudaFuncSetAttribute(augru_kernel,
                         cudaFuncAttributeMaxDynamicSharedMemorySize, SMEM_BYTES);
    dim3 grid(8, 128, 1);   // N tiles x M tiles
    augru_kernel<<<grid, TB, SMEM_BYTES>>>(x, att, hid,
                                           Wu, Uu, b_u,
                                           Wr, Ur, b_r,
                                           Wh, Uh, b_h,
                                           out);
}

// round 5
// speedup vs baseline: 1.0074x; 1.0074x over previous
#include <cuda_runtime.h>
#include <cstdint>

// ---------------------------------------------------------------------------
// Fused AUGRU cell, legacy mma.sync TF32 (sm_100-target-safe PTX).
// Round 5: (1) pre-pass rounds x/hidden/weights to tf32 into __device__
// scratch -> zero cvt in mainloop; (2) 512 threads, warp tile 32x16, occ 25%.
//   B=16384, D=H=512. CTA tile M=128 x N=64. K chunk 32, cp.async dbl-buffer.
//   Phase 0 (chunks 0-15):  A=xq,  B={Wu,Wr,Wh} -> Zu,Zr,Zx
//   Phase 1 (chunks 16-31): A=hq,  B={Uu,Ur,Uh} -> Zu,Zr,S
//   Epilogue: u=att*sig(Zu+bu), r=sig(Zr+br), hh=tanh(Zx+r*S+bh),
//             out=(1-u)*h + u*hh.
// ---------------------------------------------------------------------------

#define TB   512
#define SEG  262144                 // 512*512 floats per segment

// tf32-rounded scratch (module-load allocation; runtime-alloc-free).
__device__ float g_xq[16384 * 512];     // 32 MB
__device__ float g_hq[16384 * 512];     // 32 MB
__device__ float g_wq[6 * SEG];         // 6 MB: [Wu,Wr,Wh,Uu,Ur,Uh]

// smem (floats): A [128][36], B_w [32][72] x3, double buffered.
#define A_STRIDE   36
#define B_STRIDE   72
#define A_FLOATS   (128 * A_STRIDE)
#define B_FLOATS   (32 * B_STRIDE)
#define BUF_FLOATS (A_FLOATS + 3 * B_FLOATS)        // 11520
#define AOFF(b)    ((b) * BUF_FLOATS)
#define BOFF(b, w) ((b) * BUF_FLOATS + A_FLOATS + (w) * B_FLOATS)
#define SMEM_BYTES (2 * BUF_FLOATS * 4)             // 92160

static __device__ __forceinline__ uint32_t smem_u32(const void* p) {
    uint32_t a;
    asm("{ .reg .u64 t; cvta.to.shared.u64 t, %1; cvt.u32.u64 %0, t; }"
        : "=r"(a) : "l"(p));
    return a;
}
static __device__ __forceinline__ void cp16(uint32_t dst, const void* src) {
    asm volatile("cp.async.cg.shared.global [%0], [%1], 16;"
                 :: "r"(dst), "l"(src) : "memory");
}
static __device__ __forceinline__ void cp_commit() {
    asm volatile("cp.async.commit_group;" ::: "memory");
}
static __device__ __forceinline__ void cp_wait1() {
    asm volatile("cp.async.wait_group 1;" ::: "memory");
}
static __device__ __forceinline__ void cp_wait0() {
    asm volatile("cp.async.wait_group 0;" ::: "memory");
}
static __device__ __forceinline__ uint32_t to_tf32(float f) {
    uint32_t r;
    asm("cvt.rna.tf32.f32 %0, %1;" : "=r"(r) : "f"(f));
    return r;
}
static __device__ __forceinline__ void mma8(float* d, const uint32_t* a,
                                            const uint32_t* b) {
    asm volatile(
        "mma.sync.aligned.m16n8k8.row.col.f32.tf32.tf32.f32 "
        "{%0,%1,%2,%3}, {%4,%5,%6,%7}, {%8,%9}, {%0,%1,%2,%3};"
        : "+f"(d[0]), "+f"(d[1]), "+f"(d[2]), "+f"(d[3])
        : "r"(a[0]), "r"(a[1]), "r"(a[2]), "r"(a[3]), "r"(b[0]), "r"(b[1]));
}
static __device__ __forceinline__ float sigmoidf_fast(float z) {
    return 1.0f / (1.0f + __expf(-z));
}
static __device__ __forceinline__ float tanhf_fast(float z) {
    return 1.0f - 2.0f / (1.0f + __expf(2.0f * z));
}

// ---- pre-pass: round everything to tf32 once ------------------------------
// grid (256, 70), block 256. 70 segments of 256K floats (65536 float4).
__global__ void __launch_bounds__(256)
cvt_kernel(const float* __restrict__ x,  const float* __restrict__ hid,
           const float* __restrict__ Wu, const float* __restrict__ Wr,
           const float* __restrict__ Wh, const float* __restrict__ Uu,
           const float* __restrict__ Ur, const float* __restrict__ Uh)
{
    const int seg = blockIdx.y;
    const int i   = blockIdx.x * blockDim.x + threadIdx.x;  // float4 index
    const float* src;
    float*       dst;
    if (seg < 32)      { src = x   + (size_t)seg * SEG;        dst = g_xq + (size_t)seg * SEG; }
    else if (seg < 64) { src = hid + (size_t)(seg - 32) * SEG; dst = g_hq + (size_t)(seg - 32) * SEG; }
    else {
        const int w = seg - 64;
        const float* ws[6] = {Wu, Wr, Wh, Uu, Ur, Uh};
        src = ws[w];
        dst = g_wq + (size_t)w * SEG;
    }
    float4 v = __ldg(reinterpret_cast<const float4*>(src) + i);
    uint4 r;
    r.x = to_tf32(v.x); r.y = to_tf32(v.y);
    r.z = to_tf32(v.z); r.w = to_tf32(v.w);
    reinterpret_cast<uint4*>(dst)[i] = r;
}

// ---- main fused kernel ----------------------------------------------------
__global__ void __launch_bounds__(TB, 1)
augru_kernel(const float* __restrict__ att, const float* __restrict__ hid,
             const float* __restrict__ b_u, const float* __restrict__ b_r,
             const float* __restrict__ b_h, float* __restrict__ out)
{
    extern __shared__ float sm[];
    const uint32_t sb = smem_u32(sm);
    const int tid  = threadIdx.x;
    const int lane = tid & 31;
    const int wid  = tid >> 5;
    const int g = lane >> 2;
    const int t = lane & 3;
    const int wm = wid & 3;        // 4 warp-rows of 32
    const int wn = wid >> 2;       // 4 warp-cols of 16
    const int m0 = (int)blockIdx.y << 7;
    const int n0 = (int)blockIdx.x << 6;

    float accU[2][2][4], accR[2][2][4], accX[2][2][4], accS[2][2][4];
    #pragma unroll
    for (int mt = 0; mt < 2; mt++)
        #pragma unroll
        for (int nt = 0; nt < 2; nt++)
            #pragma unroll
            for (int e = 0; e < 4; e++) {
                accU[mt][nt][e] = 0.f; accR[mt][nt][e] = 0.f;
                accX[mt][nt][e] = 0.f; accS[mt][nt][e] = 0.f;
            }

    auto load_chunk = [&](int c, int b) {
        const int ph = (c >= 16);
        const int k0 = (c & 15) << 5;
        const float* Ap = ph ? g_hq : g_xq;
        // A: 128 x 32 floats = 1024 float4, 2 per thread.
        #pragma unroll
        for (int i = 0; i < 2; i++) {
            const int idx = tid + TB * i;
            const int row = idx >> 3;
            const int c4  = idx & 7;
            cp16(sb + (AOFF(b) + row * A_STRIDE + c4 * 4) * 4,
                 Ap + (size_t)(m0 + row) * 512 + k0 + c4 * 4);
        }
        // B: 3 weights, 32 x 64 floats = 512 float4 each, 1 per thread.
        const float* Wbase = g_wq + (size_t)(ph ? 3 : 0) * SEG;
        #pragma unroll
        for (int w = 0; w < 3; w++) {
            const float* Wp = Wbase + (size_t)w * SEG;
            const int kr = tid >> 4;
            const int n4 = tid & 15;
            cp16(sb + (BOFF(b, w) + kr * B_STRIDE + n4 * 4) * 4,
                 Wp + (size_t)(k0 + kr) * 512 + n0 + n4 * 4);
        }
        cp_commit();
    };

    load_chunk(0, 0);

    for (int c = 0; c < 32; c++) {
        const int b = c & 1;
        if (c + 1 < 32) { load_chunk(c + 1, (c + 1) & 1); cp_wait1(); }
        else            { cp_wait0(); }
        __syncthreads();

        const float* As = sm + AOFF(b) + (wm * 32) * A_STRIDE;
        const int ph = (c >= 16);

        #pragma unroll
        for (int ks = 0; ks < 4; ks++) {
            const int kc = 8 * ks + t;
            // A frags: bank = 4g + t (conflict-free), values pre-rounded.
            uint32_t a[2][4];
            #pragma unroll
            for (int mt = 0; mt < 2; mt++) {
                const float* Ar = As + (mt * 16 + g) * A_STRIDE;
                a[mt][0] = __float_as_uint(Ar[kc]);
                a[mt][1] = __float_as_uint(Ar[8 * A_STRIDE + kc]);
                a[mt][2] = __float_as_uint(Ar[kc + 4]);
                a[mt][3] = __float_as_uint(Ar[8 * A_STRIDE + kc + 4]);
            }
            // B frags: bank = 8t + g (conflict-free).
            uint32_t bb[3][2][2];
            #pragma unroll
            for (int w = 0; w < 3; w++) {
                const float* Bs = sm + BOFF(b, w) + kc * B_STRIDE + wn * 16 + g;
                #pragma unroll
                for (int nt = 0; nt < 2; nt++) {
                    bb[w][nt][0] = __float_as_uint(Bs[8 * nt]);
                    bb[w][nt][1] = __float_as_uint(Bs[4 * B_STRIDE + 8 * nt]);
                }
            }
            #pragma unroll
            for (int mt = 0; mt < 2; mt++)
                #pragma unroll
                for (int nt = 0; nt < 2; nt++) {
                    mma8(accU[mt][nt], a[mt], bb[0][nt]);
                    mma8(accR[mt][nt], a[mt], bb[1][nt]);
                    if (!ph) mma8(accX[mt][nt], a[mt], bb[2][nt]);
                    else     mma8(accS[mt][nt], a[mt], bb[2][nt]);
                }
        }
        __syncthreads();
    }

    // ---- epilogue ----------------------------------------------------------
    #pragma unroll
    for (int mt = 0; mt < 2; mt++) {
        #pragma unroll
        for (int er = 0; er < 2; er++) {
            const int m = m0 + wm * 32 + mt * 16 + g + er * 8;
            const float am = __ldg(att + m);
            const float* hrow = hid + (size_t)m * 512;
            float*       orow = out + (size_t)m * 512;
            #pragma unroll
            for (int nt = 0; nt < 2; nt++) {
                const int col = n0 + wn * 16 + nt * 8 + t * 2;
                const float2 h2  = __ldg((const float2*)(hrow + col));
                const float2 bu2 = __ldg((const float2*)(b_u + col));
                const float2 br2 = __ldg((const float2*)(b_r + col));
                const float2 bh2 = __ldg((const float2*)(b_h + col));
                float o[2];
                #pragma unroll
                for (int ec = 0; ec < 2; ec++) {
                    const int e = er * 2 + ec;
                    const float zu = accU[mt][nt][e] + (ec ? bu2.y : bu2.x);
                    const float zr = accR[mt][nt][e] + (ec ? br2.y : br2.x);
                    const float u  = am * sigmoidf_fast(zu);
                    const float r  = sigmoidf_fast(zr);
                    const float hh = tanhf_fast(accX[mt][nt][e] +
                                                r * accS[mt][nt][e] +
                                                (ec ? bh2.y : bh2.x));
                    const float hv = ec ? h2.y : h2.x;
                    o[ec] = (1.0f - u) * hv + u * hh;
                }
                *(float2*)(orow + col) = make_float2(o[0], o[1]);
            }
        }
    }
}

extern "C" void kernel_launch(void* const* d_in, const int* in_sizes, int n_in,
                              void* d_out, int out_size) {
    (void)in_sizes; (void)n_in; (void)out_size;
    const float* x   = (const float*)d_in[0];
    const float* att = (const float*)d_in[1];
    const float* hid = (const float*)d_in[2];
    const float* Wu  = (const float*)d_in[3];
    const float* Uu  = (const float*)d_in[4];
    const float* b_u = (const float*)d_in[5];
    const float* Wr  = (const float*)d_in[6];
    const float* Ur  = (const float*)d_in[7];
    const float* b_r = (const float*)d_in[8];
    const float* Wh  = (const float*)d_in[9];
    const float* Uh  = (const float*)d_in[10];
    const float* b_h = (const float*)d_in[11];
    float* out = (float*)d_out;

    cvt_kernel<<<dim3(256, 70), 256>>>(x, hid, Wu, Wr, Wh, Uu, Ur, Uh);

    cudaFuncSetAttribute(augru_kernel,
                         cudaFuncAttributeMaxDynamicSharedMemorySize, SMEM_BYTES);
    dim3 grid(8, 128, 1);
    augru_kernel<<<grid, TB, SMEM_BYTES>>>(att, hid, b_u, b_r, b_h, out);
}

// round 6
// speedup vs baseline: 1.0943x; 1.0863x over previous
#include <cuda_runtime.h>
#include <cstdint>

// ---------------------------------------------------------------------------
// Fused AUGRU cell, mma.sync TF32 (sm_100-target-safe PTX).
// Round 6: pre-pass permutes x/hidden/weights into *fragment order* so every
// mainloop fragment load is a single LDS.128 (was 4x LDS.32 gathers).
//   B=16384, D=H=512. CTA tile M=128 x N=64, 512 thr = 16 warps (4m x 4n),
//   warp tile 32x16. K chunk 32, 3-stage cp.async pipeline, 1 barrier/chunk.
//   Phase 0 (chunks 0-15):  A=xq,  B={Wu,Wr,Wh} -> Zu,Zr,Zx
//   Phase 1 (chunks 16-31): A=hq,  B={Uu,Ur,Uh} -> Zu,Zr,S
// A_perm layout:  [mB=m/16][kc=k/32][ks=0..3][lane][4]   (16B groups)
//   group(lane=(g,t)) = { A[mB*16+g][kc*32+ks*8+t],  A[..+8][..],
//                         A[mB*16+g][..+t+4],        A[..+8][..+t+4] }
// B_perm layout:  [kc][nb=n/64][ks][wn=0..3][lane][4]
//   group = { W[k][n], W[k+4][n], W[k][n+8], W[k+4][n+8] },
//   k = kc*32+ks*8+t, n = nb*64+wn*16+g.
// ---------------------------------------------------------------------------

#define TB   512
#define SEG  262144                     // 512*512 floats

__device__ float g_xa[16384 * 512];     // x, fragment-permuted tf32
__device__ float g_ha[16384 * 512];     // hidden, fragment-permuted tf32
__device__ float g_wb[6 * SEG];         // Wu,Wr,Wh,Uu,Ur,Uh permuted tf32

// smem: per buffer A 16KB (1024 groups) + 3x B 8KB (512 groups) = 40KB, x3.
#define A_BYTES    16384
#define B_BYTES    8192
#define BUF_BYTES  40960
#define SMEM_BYTES (3 * BUF_BYTES)      // 122880

static __device__ __forceinline__ uint32_t smem_u32(const void* p) {
    uint32_t a;
    asm("{ .reg .u64 t; cvta.to.shared.u64 t, %1; cvt.u32.u64 %0, t; }"
        : "=r"(a) : "l"(p));
    return a;
}
static __device__ __forceinline__ void cp16(uint32_t dst, const void* src) {
    asm volatile("cp.async.cg.shared.global [%0], [%1], 16;"
                 :: "r"(dst), "l"(src) : "memory");
}
static __device__ __forceinline__ void cp_commit() {
    asm volatile("cp.async.commit_group;" ::: "memory");
}
static __device__ __forceinline__ void cp_wait1() {
    asm volatile("cp.async.wait_group 1;" ::: "memory");
}
static __device__ __forceinline__ void cp_wait0() {
    asm volatile("cp.async.wait_group 0;" ::: "memory");
}
static __device__ __forceinline__ uint32_t to_tf32(float f) {
    uint32_t r;
    asm("cvt.rna.tf32.f32 %0, %1;" : "=r"(r) : "f"(f));
    return r;
}
static __device__ __forceinline__ void mma8(float* d, const uint32_t* a,
                                            uint32_t b0, uint32_t b1) {
    asm volatile(
        "mma.sync.aligned.m16n8k8.row.col.f32.tf32.tf32.f32 "
        "{%0,%1,%2,%3}, {%4,%5,%6,%7}, {%8,%9}, {%0,%1,%2,%3};"
        : "+f"(d[0]), "+f"(d[1]), "+f"(d[2]), "+f"(d[3])
        : "r"(a[0]), "r"(a[1]), "r"(a[2]), "r"(a[3]), "r"(b0), "r"(b1));
}
static __device__ __forceinline__ float sigmoidf_fast(float z) {
    return 1.0f / (1.0f + __expf(-z));
}
static __device__ __forceinline__ float tanhf_fast(float z) {
    return 1.0f - 2.0f / (1.0f + __expf(2.0f * z));
}

// ---- pre-pass: permute A matrices (x, hidden) into fragment order ---------
// grid (8192, 2), block 256. 2^21 16B-groups per matrix.
__global__ void __launch_bounds__(256)
permA_kernel(const float* __restrict__ x, const float* __restrict__ hid)
{
    const int gi  = blockIdx.x * 256 + threadIdx.x;
    const float* src = blockIdx.y ? hid : x;
    float*       dst = blockIdx.y ? g_ha : g_xa;
    const int mB   = gi >> 11;
    const int rem  = gi & 2047;
    const int kc   = rem >> 7;
    const int low  = rem & 127;          // ks*32 + lane
    const int ks   = low >> 5;
    const int lane = low & 31;
    const int g = lane >> 2, t = lane & 3;
    const int r = mB * 16 + g;
    const int k = kc * 32 + ks * 8 + t;
    uint4 o;
    o.x = to_tf32(__ldg(src + (size_t)r * 512 + k));
    o.y = to_tf32(__ldg(src + (size_t)(r + 8) * 512 + k));
    o.z = to_tf32(__ldg(src + (size_t)r * 512 + k + 4));
    o.w = to_tf32(__ldg(src + (size_t)(r + 8) * 512 + k + 4));
    reinterpret_cast<uint4*>(dst)[gi] = o;
}

// ---- pre-pass: permute weights into fragment order -------------------------
// grid (256, 6), block 256. 65536 groups per matrix.
__global__ void __launch_bounds__(256)
permB_kernel(const float* __restrict__ Wu, const float* __restrict__ Wr,
             const float* __restrict__ Wh, const float* __restrict__ Uu,
             const float* __restrict__ Ur, const float* __restrict__ Uh)
{
    const int gi = blockIdx.x * 256 + threadIdx.x;
    const int w  = blockIdx.y;
    const float* ws[6] = {Wu, Wr, Wh, Uu, Ur, Uh};
    const float* src = ws[w];
    float*       dst = g_wb + (size_t)w * SEG;
    const int kc   = gi >> 12;
    const int rem  = gi & 4095;
    const int nb   = rem >> 9;
    const int ks   = (rem >> 7) & 3;
    const int wn   = (rem >> 5) & 3;
    const int lane = rem & 31;
    const int g = lane >> 2, t = lane & 3;
    const int k = kc * 32 + ks * 8 + t;
    const int n = nb * 64 + wn * 16 + g;
    uint4 o;
    o.x = to_tf32(__ldg(src + (size_t)k * 512 + n));
    o.y = to_tf32(__ldg(src + (size_t)(k + 4) * 512 + n));
    o.z = to_tf32(__ldg(src + (size_t)k * 512 + n + 8));
    o.w = to_tf32(__ldg(src + (size_t)(k + 4) * 512 + n + 8));
    reinterpret_cast<uint4*>(dst)[gi] = o;
}

// ---- main fused kernel ----------------------------------------------------
__global__ void __launch_bounds__(TB, 1)
augru_kernel(const float* __restrict__ att, const float* __restrict__ hid,
             const float* __restrict__ b_u, const float* __restrict__ b_r,
             const float* __restrict__ b_h, float* __restrict__ out)
{
    extern __shared__ float sm[];
    const uint32_t sb = smem_u32(sm);
    const int tid  = threadIdx.x;
    const int lane = tid & 31;
    const int wid  = tid >> 5;
    const int g = lane >> 2;
    const int t = lane & 3;
    const int wm = wid & 3;        // 4 warp-rows of 32
    const int wn = wid >> 2;       // 4 warp-cols of 16
    const int m0 = (int)blockIdx.y << 7;
    const int n0 = (int)blockIdx.x << 6;
    const int mB0 = m0 >> 4;
    const int nb  = n0 >> 6;

    float accU[2][2][4], accR[2][2][4], accX[2][2][4], accS[2][2][4];
    #pragma unroll
    for (int mt = 0; mt < 2; mt++)
        #pragma unroll
        for (int nt = 0; nt < 2; nt++)
            #pragma unroll
            for (int e = 0; e < 4; e++) {
                accU[mt][nt][e] = 0.f; accR[mt][nt][e] = 0.f;
                accX[mt][nt][e] = 0.f; accS[mt][nt][e] = 0.f;
            }

    auto load_chunk = [&](int c, int b) {
        const int ph = (c >= 16);
        const int kc = c & 15;
        const uint32_t bo = sb + (uint32_t)b * BUF_BYTES;
        // A: 1024 groups, 2 per thread.
        const uint4* Ag = reinterpret_cast<const uint4*>(ph ? g_ha : g_xa);
        #pragma unroll
        for (int i = 0; i < 2; i++) {
            const int idx = tid + TB * i;
            const int mb  = idx >> 7;
            const int low = idx & 127;
            cp16(bo + idx * 16,
                 Ag + ((size_t)(mB0 + mb) * 2048 + kc * 128 + low));
        }
        // B: 3 weights, 512 groups each, 1 per thread.
        const uint4* Bg = reinterpret_cast<const uint4*>(g_wb)
                        + (size_t)(ph ? 3 : 0) * (SEG / 4);
        #pragma unroll
        for (int w = 0; w < 3; w++) {
            cp16(bo + A_BYTES + w * B_BYTES + tid * 16,
                 Bg + (size_t)w * (SEG / 4) + kc * 4096 + nb * 512 + tid);
        }
        cp_commit();
    };

    load_chunk(0, 0);
    load_chunk(1, 1);

    for (int c = 0; c < 32; c++) {
        const int b = c % 3;
        if (c == 31) cp_wait0(); else cp_wait1();
        __syncthreads();
        if (c + 2 < 32) load_chunk(c + 2, (c + 2) % 3);

        const float* Ab = sm + (size_t)b * (BUF_BYTES / 4);
        const float* Bb = Ab + (A_BYTES / 4);
        const int ph = (c >= 16);

        #pragma unroll
        for (int ks = 0; ks < 4; ks++) {
            uint32_t a[2][4];
            #pragma unroll
            for (int mt = 0; mt < 2; mt++) {
                const int mb = wm * 2 + mt;
                const float4 av = *reinterpret_cast<const float4*>(
                    Ab + ((mb * 4 + ks) * 32 + lane) * 4);
                a[mt][0] = __float_as_uint(av.x);
                a[mt][1] = __float_as_uint(av.y);
                a[mt][2] = __float_as_uint(av.z);
                a[mt][3] = __float_as_uint(av.w);
            }
            uint32_t bb[3][4];
            #pragma unroll
            for (int w = 0; w < 3; w++) {
                const float4 bv = *reinterpret_cast<const float4*>(
                    Bb + w * (B_BYTES / 4) + ((ks * 4 + wn) * 32 + lane) * 4);
                bb[w][0] = __float_as_uint(bv.x);
                bb[w][1] = __float_as_uint(bv.y);
                bb[w][2] = __float_as_uint(bv.z);
                bb[w][3] = __float_as_uint(bv.w);
            }
            #pragma unroll
            for (int mt = 0; mt < 2; mt++)
                #pragma unroll
                for (int nt = 0; nt < 2; nt++) {
                    mma8(accU[mt][nt], a[mt], bb[0][2 * nt], bb[0][2 * nt + 1]);
                    mma8(accR[mt][nt], a[mt], bb[1][2 * nt], bb[1][2 * nt + 1]);
                    if (!ph)
                        mma8(accX[mt][nt], a[mt], bb[2][2 * nt], bb[2][2 * nt + 1]);
                    else
                        mma8(accS[mt][nt], a[mt], bb[2][2 * nt], bb[2][2 * nt + 1]);
                }
        }
    }

    // ---- epilogue ----------------------------------------------------------
    #pragma unroll
    for (int mt = 0; mt < 2; mt++) {
        #pragma unroll
        for (int er = 0; er < 2; er++) {
            const int m = m0 + wm * 32 + mt * 16 + g + er * 8;
            const float am = __ldg(att + m);
            const float* hrow = hid + (size_t)m * 512;
            float*       orow = out + (size_t)m * 512;
            #pragma unroll
            for (int nt = 0; nt < 2; nt++) {
                const int col = n0 + wn * 16 + nt * 8 + t * 2;
                const float2 h2  = __ldg((const float2*)(hrow + col));
                const float2 bu2 = __ldg((const float2*)(b_u + col));
                const float2 br2 = __ldg((const float2*)(b_r + col));
                const float2 bh2 = __ldg((const float2*)(b_h + col));
                float o[2];
                #pragma unroll
                for (int ec = 0; ec < 2; ec++) {
                    const int e = er * 2 + ec;
                    const float zu = accU[mt][nt][e] + (ec ? bu2.y : bu2.x);
                    const float zr = accR[mt][nt][e] + (ec ? br2.y : br2.x);
                    const float u  = am * sigmoidf_fast(zu);
                    const float r  = sigmoidf_fast(zr);
                    const float hh = tanhf_fast(accX[mt][nt][e] +
                                                r * accS[mt][nt][e] +
                                                (ec ? bh2.y : bh2.x));
                    const float hv = ec ? h2.y : h2.x;
                    o[ec] = (1.0f - u) * hv + u * hh;
                }
                *(float2*)(orow + col) = make_float2(o[0], o[1]);
            }
        }
    }
}

extern "C" void kernel_launch(void* const* d_in, const int* in_sizes, int n_in,
                              void* d_out, int out_size) {
    (void)in_sizes; (void)n_in; (void)out_size;
    const float* x   = (const float*)d_in[0];
    const float* att = (const float*)d_in[1];
    const float* hid = (const float*)d_in[2];
    const float* Wu  = (const float*)d_in[3];
    const float* Uu  = (const float*)d_in[4];
    const float* b_u = (const float*)d_in[5];
    const float* Wr  = (const float*)d_in[6];
    const float* Ur  = (const float*)d_in[7];
    const float* b_r = (const float*)d_in[8];
    const float* Wh  = (const float*)d_in[9];
    const float* Uh  = (const float*)d_in[10];
    const float* b_h = (const float*)d_in[11];
    float* out = (float*)d_out;

    permA_kernel<<<dim3(8192, 2), 256>>>(x, hid);
    permB_kernel<<<dim3(256, 6), 256>>>(Wu, Wr, Wh, Uu, Ur, Uh);

    cudaFuncSetAttribute(augru_kernel,
                         cudaFuncAttributeMaxDynamicSharedMemorySize, SMEM_BYTES);
    dim3 grid(8, 128, 1);
    augru_kernel<<<grid, TB, SMEM_BYTES>>>(att, hid, b_u, b_r, b_h, out);
}

// round 7
// speedup vs baseline: 1.0956x; 1.0012x over previous
#include <cuda_runtime.h>
#include <cstdint>

// ---------------------------------------------------------------------------
// Fused AUGRU cell, mma.sync TF32 (sm_100-target-safe PTX).
// Round 6: pre-pass permutes x/hidden/weights into *fragment order* so every
// mainloop fragment load is a single LDS.128 (was 4x LDS.32 gathers).
//   B=16384, D=H=512. CTA tile M=128 x N=64, 512 thr = 16 warps (4m x 4n),
//   warp tile 32x16. K chunk 32, 3-stage cp.async pipeline, 1 barrier/chunk.
//   Phase 0 (chunks 0-15):  A=xq,  B={Wu,Wr,Wh} -> Zu,Zr,Zx
//   Phase 1 (chunks 16-31): A=hq,  B={Uu,Ur,Uh} -> Zu,Zr,S
// A_perm layout:  [mB=m/16][kc=k/32][ks=0..3][lane][4]   (16B groups)
//   group(lane=(g,t)) = { A[mB*16+g][kc*32+ks*8+t],  A[..+8][..],
//                         A[mB*16+g][..+t+4],        A[..+8][..+t+4] }
// B_perm layout:  [kc][nb=n/64][ks][wn=0..3][lane][4]
//   group = { W[k][n], W[k+4][n], W[k][n+8], W[k+4][n+8] },
//   k = kc*32+ks*8+t, n = nb*64+wn*16+g.
// ---------------------------------------------------------------------------

#define TB   512
#define SEG  262144                     // 512*512 floats

__device__ float g_xa[16384 * 512];     // x, fragment-permuted tf32
__device__ float g_ha[16384 * 512];     // hidden, fragment-permuted tf32
__device__ float g_wb[6 * SEG];         // Wu,Wr,Wh,Uu,Ur,Uh permuted tf32

// smem: per buffer A 16KB (1024 groups) + 3x B 8KB (512 groups) = 40KB, x3.
#define A_BYTES    16384
#define B_BYTES    8192
#define BUF_BYTES  40960
#define SMEM_BYTES (3 * BUF_BYTES)      // 122880

static __device__ __forceinline__ uint32_t smem_u32(const void* p) {
    uint32_t a;
    asm("{ .reg .u64 t; cvta.to.shared.u64 t, %1; cvt.u32.u64 %0, t; }"
        : "=r"(a) : "l"(p));
    return a;
}
static __device__ __forceinline__ void cp16(uint32_t dst, const void* src) {
    asm volatile("cp.async.cg.shared.global [%0], [%1], 16;"
                 :: "r"(dst), "l"(src) : "memory");
}
static __device__ __forceinline__ void cp_commit() {
    asm volatile("cp.async.commit_group;" ::: "memory");
}
static __device__ __forceinline__ void cp_wait1() {
    asm volatile("cp.async.wait_group 1;" ::: "memory");
}
static __device__ __forceinline__ void cp_wait0() {
    asm volatile("cp.async.wait_group 0;" ::: "memory");
}
static __device__ __forceinline__ uint32_t to_tf32(float f) {
    uint32_t r;
    asm("cvt.rna.tf32.f32 %0, %1;" : "=r"(r) : "f"(f));
    return r;
}
static __device__ __forceinline__ void mma8(float* d, const uint32_t* a,
                                            uint32_t b0, uint32_t b1) {
    asm volatile(
        "mma.sync.aligned.m16n8k8.row.col.f32.tf32.tf32.f32 "
        "{%0,%1,%2,%3}, {%4,%5,%6,%7}, {%8,%9}, {%0,%1,%2,%3};"
        : "+f"(d[0]), "+f"(d[1]), "+f"(d[2]), "+f"(d[3])
        : "r"(a[0]), "r"(a[1]), "r"(a[2]), "r"(a[3]), "r"(b0), "r"(b1));
}
static __device__ __forceinline__ float sigmoidf_fast(float z) {
    return 1.0f / (1.0f + __expf(-z));
}
static __device__ __forceinline__ float tanhf_fast(float z) {
    return 1.0f - 2.0f / (1.0f + __expf(2.0f * z));
}

// ---- pre-pass: permute A matrices (x, hidden) into fragment order ---------
// grid (8192, 2), block 256. 2^21 16B-groups per matrix.
__global__ void __launch_bounds__(256)
permA_kernel(const float* __restrict__ x, const float* __restrict__ hid)
{
    const int gi  = blockIdx.x * 256 + threadIdx.x;
    const float* src = blockIdx.y ? hid : x;
    float*       dst = blockIdx.y ? g_ha : g_xa;
    const int mB   = gi >> 11;
    const int rem  = gi & 2047;
    const int kc   = rem >> 7;
    const int low  = rem & 127;          // ks*32 + lane
    const int ks   = low >> 5;
    const int lane = low & 31;
    const int g = lane >> 2, t = lane & 3;
    const int r = mB * 16 + g;
    const int k = kc * 32 + ks * 8 + t;
    uint4 o;
    o.x = to_tf32(__ldg(src + (size_t)r * 512 + k));
    o.y = to_tf32(__ldg(src + (size_t)(r + 8) * 512 + k));
    o.z = to_tf32(__ldg(src + (size_t)r * 512 + k + 4));
    o.w = to_tf32(__ldg(src + (size_t)(r + 8) * 512 + k + 4));
    reinterpret_cast<uint4*>(dst)[gi] = o;
}

// ---- pre-pass: permute weights into fragment order -------------------------
// grid (256, 6), block 256. 65536 groups per matrix.
__global__ void __launch_bounds__(256)
permB_kernel(const float* __restrict__ Wu, const float* __restrict__ Wr,
             const float* __restrict__ Wh, const float* __restrict__ Uu,
             const float* __restrict__ Ur, const float* __restrict__ Uh)
{
    const int gi = blockIdx.x * 256 + threadIdx.x;
    const int w  = blockIdx.y;
    const float* ws[6] = {Wu, Wr, Wh, Uu, Ur, Uh};
    const float* src = ws[w];
    float*       dst = g_wb + (size_t)w * SEG;
    const int kc   = gi >> 12;
    const int rem  = gi & 4095;
    const int nb   = rem >> 9;
    const int ks   = (rem >> 7) & 3;
    const int wn   = (rem >> 5) & 3;
    const int lane = rem & 31;
    const int g = lane >> 2, t = lane & 3;
    const int k = kc * 32 + ks * 8 + t;
    const int n = nb * 64 + wn * 16 + g;
    uint4 o;
    o.x = to_tf32(__ldg(src + (size_t)k * 512 + n));
    o.y = to_tf32(__ldg(src + (size_t)(k + 4) * 512 + n));
    o.z = to_tf32(__ldg(src + (size_t)k * 512 + n + 8));
    o.w = to_tf32(__ldg(src + (size_t)(k + 4) * 512 + n + 8));
    reinterpret_cast<uint4*>(dst)[gi] = o;
}

// ---- main fused kernel ----------------------------------------------------
__global__ void __launch_bounds__(TB, 1)
augru_kernel(const float* __restrict__ att, const float* __restrict__ hid,
             const float* __restrict__ b_u, const float* __restrict__ b_r,
             const float* __restrict__ b_h, float* __restrict__ out)
{
    extern __shared__ float sm[];
    const uint32_t sb = smem_u32(sm);
    const int tid  = threadIdx.x;
    const int lane = tid & 31;
    const int wid  = tid >> 5;
    const int g = lane >> 2;
    const int t = lane & 3;
    const int wm = wid & 3;        // 4 warp-rows of 32
    const int wn = wid >> 2;       // 4 warp-cols of 16
    const int m0 = (int)blockIdx.y << 7;
    const int n0 = (int)blockIdx.x << 6;
    const int mB0 = m0 >> 4;
    const int nb  = n0 >> 6;

    float accU[2][2][4], accR[2][2][4], accX[2][2][4], accS[2][2][4];
    #pragma unroll
    for (int mt = 0; mt < 2; mt++)
        #pragma unroll
        for (int nt = 0; nt < 2; nt++)
            #pragma unroll
            for (int e = 0; e < 4; e++) {
                accU[mt][nt][e] = 0.f; accR[mt][nt][e] = 0.f;
                accX[mt][nt][e] = 0.f; accS[mt][nt][e] = 0.f;
            }

    auto load_chunk = [&](int c, int b) {
        const int ph = (c >= 16);
        const int kc = c & 15;
        const uint32_t bo = sb + (uint32_t)b * BUF_BYTES;
        // A: 1024 groups, 2 per thread.
        const uint4* Ag = reinterpret_cast<const uint4*>(ph ? g_ha : g_xa);
        #pragma unroll
        for (int i = 0; i < 2; i++) {
            const int idx = tid + TB * i;
            const int mb  = idx >> 7;
            const int low = idx & 127;
            cp16(bo + idx * 16,
                 Ag + ((size_t)(mB0 + mb) * 2048 + kc * 128 + low));
        }
        // B: 3 weights, 512 groups each, 1 per thread.
        const uint4* Bg = reinterpret_cast<const uint4*>(g_wb)
                        + (size_t)(ph ? 3 : 0) * (SEG / 4);
        #pragma unroll
        for (int w = 0; w < 3; w++) {
            cp16(bo + A_BYTES + w * B_BYTES + tid * 16,
                 Bg + (size_t)w * (SEG / 4) + kc * 4096 + nb * 512 + tid);
        }
        cp_commit();
    };

    load_chunk(0, 0);
    load_chunk(1, 1);

    for (int c = 0; c < 32; c++) {
        const int b = c % 3;
        if (c == 31) cp_wait0(); else cp_wait1();
        __syncthreads();
        if (c + 2 < 32) load_chunk(c + 2, (c + 2) % 3);

        const float* Ab = sm + (size_t)b * (BUF_BYTES / 4);
        const float* Bb = Ab + (A_BYTES / 4);
        const int ph = (c >= 16);

        #pragma unroll
        for (int ks = 0; ks < 4; ks++) {
            uint32_t a[2][4];
            #pragma unroll
            for (int mt = 0; mt < 2; mt++) {
                const int mb = wm * 2 + mt;
                const float4 av = *reinterpret_cast<const float4*>(
                    Ab + ((mb * 4 + ks) * 32 + lane) * 4);
                a[mt][0] = __float_as_uint(av.x);
                a[mt][1] = __float_as_uint(av.y);
                a[mt][2] = __float_as_uint(av.z);
                a[mt][3] = __float_as_uint(av.w);
            }
            uint32_t bb[3][4];
            #pragma unroll
            for (int w = 0; w < 3; w++) {
                const float4 bv = *reinterpret_cast<const float4*>(
                    Bb + w * (B_BYTES / 4) + ((ks * 4 + wn) * 32 + lane) * 4);
                bb[w][0] = __float_as_uint(bv.x);
                bb[w][1] = __float_as_uint(bv.y);
                bb[w][2] = __float_as_uint(bv.z);
                bb[w][3] = __float_as_uint(bv.w);
            }
            #pragma unroll
            for (int mt = 0; mt < 2; mt++)
                #pragma unroll
                for (int nt = 0; nt < 2; nt++) {
                    mma8(accU[mt][nt], a[mt], bb[0][2 * nt], bb[0][2 * nt + 1]);
                    mma8(accR[mt][nt], a[mt], bb[1][2 * nt], bb[1][2 * nt + 1]);
                    if (!ph)
                        mma8(accX[mt][nt], a[mt], bb[2][2 * nt], bb[2][2 * nt + 1]);
                    else
                        mma8(accS[mt][nt], a[mt], bb[2][2 * nt], bb[2][2 * nt + 1]);
                }
        }
    }

    // ---- epilogue ----------------------------------------------------------
    #pragma unroll
    for (int mt = 0; mt < 2; mt++) {
        #pragma unroll
        for (int er = 0; er < 2; er++) {
            const int m = m0 + wm * 32 + mt * 16 + g + er * 8;
            const float am = __ldg(att + m);
            const float* hrow = hid + (size_t)m * 512;
            float*       orow = out + (size_t)m * 512;
            #pragma unroll
            for (int nt = 0; nt < 2; nt++) {
                const int col = n0 + wn * 16 + nt * 8 + t * 2;
                const float2 h2  = __ldg((const float2*)(hrow + col));
                const float2 bu2 = __ldg((const float2*)(b_u + col));
                const float2 br2 = __ldg((const float2*)(b_r + col));
                const float2 bh2 = __ldg((const float2*)(b_h + col));
                float o[2];
                #pragma unroll
                for (int ec = 0; ec < 2; ec++) {
                    const int e = er * 2 + ec;
                    const float zu = accU[mt][nt][e] + (ec ? bu2.y : bu2.x);
                    const float zr = accR[mt][nt][e] + (ec ? br2.y : br2.x);
                    const float u  = am * sigmoidf_fast(zu);
                    const float r  = sigmoidf_fast(zr);
                    const float hh = tanhf_fast(accX[mt][nt][e] +
                                                r * accS[mt][nt][e] +
                                                (ec ? bh2.y : bh2.x));
                    const float hv = ec ? h2.y : h2.x;
                    o[ec] = (1.0f - u) * hv + u * hh;
                }
                *(float2*)(orow + col) = make_float2(o[0], o[1]);
            }
        }
    }
}

extern "C" void kernel_launch(void* const* d_in, const int* in_sizes, int n_in,
                              void* d_out, int out_size) {
    (void)in_sizes; (void)n_in; (void)out_size;
    const float* x   = (const float*)d_in[0];
    const float* att = (const float*)d_in[1];
    const float* hid = (const float*)d_in[2];
    const float* Wu  = (const float*)d_in[3];
    const float* Uu  = (const float*)d_in[4];
    const float* b_u = (const float*)d_in[5];
    const float* Wr  = (const float*)d_in[6];
    const float* Ur  = (const float*)d_in[7];
    const float* b_r = (const float*)d_in[8];
    const float* Wh  = (const float*)d_in[9];
    const float* Uh  = (const float*)d_in[10];
    const float* b_h = (const float*)d_in[11];
    float* out = (float*)d_out;

    permA_kernel<<<dim3(8192, 2), 256>>>(x, hid);
    permB_kernel<<<dim3(256, 6), 256>>>(Wu, Wr, Wh, Uu, Ur, Uh);

    cudaFuncSetAttribute(augru_kernel,
                         cudaFuncAttributeMaxDynamicSharedMemorySize, SMEM_BYTES);
    dim3 grid(8, 128, 1);
    augru_kernel<<<grid, TB, SMEM_BYTES>>>(att, hid, b_u, b_r, b_h, out);
}

// round 10
// speedup vs baseline: 1.7757x; 1.6207x over previous
#include <cuda_runtime.h>
#include <cuda_fp16.h>
#include <cstdint>

// ---------------------------------------------------------------------------
// Fused AUGRU cell, mma.sync FP16 (m16n8k16) — same 10-bit mantissa as tf32.
// Pre-pass converts+permutes x/hidden/weights into fp16 *fragment order*:
// every mainloop fragment load is one LDS.128; HMMA count halved vs tf32.
//   B=16384, D=H=512. CTA tile M=128 x N=64, 512 thr = 16 warps (4m x 4n),
//   warp tile 32x16. K chunk 32, 4-stage cp.async pipeline.
//   Phase 0 (chunks 0-15):  A=x,  B={Wu,Wr,Wh} -> Zu,Zr,Zx
//   Phase 1 (chunks 16-31): A=h,  B={Uu,Ur,Uh} -> Zu,Zr,S
// A group (16B, 8 fp16) = m16n8k16 A-fragment of thread (g,t):
//   { A[r][k],A[r][k+1] | A[r+8][k],A[r+8][k+1] |
//     A[r][k+8],A[r][k+9] | A[r+8][k+8],A[r+8][k+9] },  r=mB*16+g, k=base+2t.
// B group (16B) = fragments for two n8 tiles:
//   { W[k][n],W[k+1][n] | W[k+8][n],W[k+9][n] |
//     W[k][n+8],W[k+1][n+8] | W[k+8][n+8],W[k+9][n+8] }, n=nb*64+wn*16+g.
// ---------------------------------------------------------------------------

#define TB 512

__device__ uint4 g_xa[1048576];   // x  fragment-permuted fp16 (16 MB)
__device__ uint4 g_ha[1048576];   // h  fragment-permuted fp16 (16 MB)
__device__ uint4 g_wb[196608];    // weights, [ph][kc][nb][w][ks][wn][lane] (3 MB)

#define A_BYTES    8192
#define B_BYTES    12288
#define BUF_BYTES  20480
#define SMEM_BYTES (4 * BUF_BYTES)    // 81920

static __device__ __forceinline__ uint32_t smem_u32(const void* p) {
    uint32_t a;
    asm("{ .reg .u64 t; cvta.to.shared.u64 t, %1; cvt.u32.u64 %0, t; }"
        : "=r"(a) : "l"(p));
    return a;
}
static __device__ __forceinline__ void cp16(uint32_t dst, const void* src) {
    asm volatile("cp.async.cg.shared.global [%0], [%1], 16;"
                 :: "r"(dst), "l"(src) : "memory");
}
static __device__ __forceinline__ void cp_commit() {
    asm volatile("cp.async.commit_group;" ::: "memory");
}
static __device__ __forceinline__ void cp_waitn(int rem) {
    if (rem >= 2)      asm volatile("cp.async.wait_group 2;" ::: "memory");
    else if (rem == 1) asm volatile("cp.async.wait_group 1;" ::: "memory");
    else               asm volatile("cp.async.wait_group 0;" ::: "memory");
}
static __device__ __forceinline__ uint32_t pack2(float lo, float hi) {
    __half h0 = __float2half_rn(lo);
    __half h1 = __float2half_rn(hi);
    return ((uint32_t)__half_as_ushort(h1) << 16) | (uint32_t)__half_as_ushort(h0);
}
static __device__ __forceinline__ void mma16(float* d, const uint32_t* a,
                                             uint32_t b0, uint32_t b1) {
    asm volatile(
        "mma.sync.aligned.m16n8k16.row.col.f32.f16.f16.f32 "
        "{%0,%1,%2,%3}, {%4,%5,%6,%7}, {%8,%9}, {%0,%1,%2,%3};"
        : "+f"(d[0]), "+f"(d[1]), "+f"(d[2]), "+f"(d[3])
        : "r"(a[0]), "r"(a[1]), "r"(a[2]), "r"(a[3]), "r"(b0), "r"(b1));
}
static __device__ __forceinline__ float sigmoidf_fast(float z) {
    return 1.0f / (1.0f + __expf(-z));
}
static __device__ __forceinline__ float tanhf_fast(float z) {
    return 1.0f - 2.0f / (1.0f + __expf(2.0f * z));
}

// ---- pre-pass A: grid (4096, 2) x 256. One 16B group per thread. ----------
__global__ void __launch_bounds__(256)
permA_kernel(const float* __restrict__ x, const float* __restrict__ hid)
{
    const int gi = blockIdx.x * 256 + threadIdx.x;       // 0..1048575
    const float* src = blockIdx.y ? hid : x;
    uint4*       dst = blockIdx.y ? g_ha : g_xa;
    const int mB   = gi >> 10;
    const int rem  = gi & 1023;
    const int kc   = rem >> 6;
    const int low  = rem & 63;
    const int ks   = low >> 5;
    const int lane = low & 31;
    const int g = lane >> 2, t = lane & 3;
    const int r = mB * 16 + g;
    const int k = kc * 32 + ks * 16 + 2 * t;
    const float* p0 = src + (size_t)r * 512 + k;
    const float* p1 = src + (size_t)(r + 8) * 512 + k;
    uint4 o;
    o.x = pack2(__ldg(p0),     __ldg(p0 + 1));
    o.y = pack2(__ldg(p1),     __ldg(p1 + 1));
    o.z = pack2(__ldg(p0 + 8), __ldg(p0 + 9));
    o.w = pack2(__ldg(p1 + 8), __ldg(p1 + 9));
    dst[gi] = o;
}

// ---- pre-pass B: grid (128, 6) x 256. -------------------------------------
__global__ void __launch_bounds__(256)
permB_kernel(const float* __restrict__ Wu, const float* __restrict__ Wr,
             const float* __restrict__ Wh, const float* __restrict__ Uu,
             const float* __restrict__ Ur, const float* __restrict__ Uh)
{
    const int gi = blockIdx.x * 256 + threadIdx.x;       // 0..32767
    const int w  = blockIdx.y;
    const int ph = w / 3, w3 = w % 3;
    const float* ws[6] = {Wu, Wr, Wh, Uu, Ur, Uh};
    const float* src = ws[w];
    const int kc   = gi >> 11;
    const int rem  = gi & 2047;
    const int nb   = rem >> 8;
    const int rem2 = rem & 255;
    const int ks   = rem2 >> 7;
    const int wn   = (rem2 >> 5) & 3;
    const int lane = rem2 & 31;
    const int g = lane >> 2, t = lane & 3;
    const int k = kc * 32 + ks * 16 + 2 * t;
    const int n = nb * 64 + wn * 16 + g;
    const float* pk  = src + (size_t)k * 512 + n;
    uint4 o;
    o.x = pack2(__ldg(pk),             __ldg(pk + 512));
    o.y = pack2(__ldg(pk + 8 * 512),   __ldg(pk + 9 * 512));
    o.z = pack2(__ldg(pk + 8),         __ldg(pk + 512 + 8));
    o.w = pack2(__ldg(pk + 8 * 512 + 8), __ldg(pk + 9 * 512 + 8));
    const size_t di = ((size_t)((((ph * 16 + kc) * 8 + nb) * 3 + w3) * 2 + ks)) * 128
                    + wn * 32 + lane;
    g_wb[di] = o;
}

// ---- main fused kernel ----------------------------------------------------
__global__ void __launch_bounds__(TB, 1)
augru_kernel(const float* __restrict__ att, const float* __restrict__ hid,
             const float* __restrict__ b_u, const float* __restrict__ b_r,
             const float* __restrict__ b_h, float* __restrict__ out)
{
    extern __shared__ char smc[];
    const uint32_t sb = smem_u32(smc);
    const int tid  = threadIdx.x;
    const int lane = tid & 31;
    const int wid  = tid >> 5;
    const int g = lane >> 2;
    const int t = lane & 3;
    const int wm = wid & 3;
    const int wn = wid >> 2;
    const int m0 = (int)blockIdx.y << 7;
    const int n0 = (int)blockIdx.x << 6;
    const int mB0 = m0 >> 4;
    const int nb  = n0 >> 6;

    float accU[2][2][4], accR[2][2][4], accX[2][2][4], accS[2][2][4];
    #pragma unroll
    for (int mt = 0; mt < 2; mt++)
        #pragma unroll
        for (int nt = 0; nt < 2; nt++)
            #pragma unroll
            for (int e = 0; e < 4; e++) {
                accU[mt][nt][e] = 0.f; accR[mt][nt][e] = 0.f;
                accX[mt][nt][e] = 0.f; accS[mt][nt][e] = 0.f;
            }

    auto load_chunk = [&](int c, int b) {
        const int ph = (c >= 16);
        const int kc = c & 15;
        const uint32_t bo = sb + (uint32_t)b * BUF_BYTES;
        // A: 512 groups, 1 per thread. [mb=8][ks=2][lane=32] per (mB,kc).
        const uint4* Ag = ph ? g_ha : g_xa;
        {
            const int mb  = tid >> 6;
            const int low = tid & 63;
            cp16(bo + tid * 16,
                 Ag + ((size_t)(mB0 + mb) * 1024 + kc * 64 + low));
        }
        // B: 768 contiguous groups for this (ph,kc,nb).
        const uint4* Bg = g_wb + ((size_t)((ph * 16 + kc) * 8 + nb)) * 768;
        cp16(bo + A_BYTES + tid * 16, Bg + tid);
        if (tid < 256)
            cp16(bo + A_BYTES + (512 + tid) * 16, Bg + 512 + tid);
        cp_commit();
    };

    load_chunk(0, 0);
    load_chunk(1, 1);
    load_chunk(2, 2);

    for (int c = 0; c < 32; c++) {
        const int b = c & 3;
        cp_waitn(31 - c);
        __syncthreads();
        if (c + 3 < 32) load_chunk(c + 3, (c + 3) & 3);

        const uint4* Ab4 = reinterpret_cast<const uint4*>(smc + b * BUF_BYTES);
        const uint4* Bb4 = reinterpret_cast<const uint4*>(smc + b * BUF_BYTES + A_BYTES);
        const int ph = (c >= 16);

        #pragma unroll
        for (int ks = 0; ks < 2; ks++) {
            uint32_t a[2][4];
            #pragma unroll
            for (int mt = 0; mt < 2; mt++) {
                const int mb = wm * 2 + mt;
                const uint4 av = Ab4[mb * 64 + ks * 32 + lane];
                a[mt][0] = av.x; a[mt][1] = av.y; a[mt][2] = av.z; a[mt][3] = av.w;
            }
            uint4 bv[3];
            #pragma unroll
            for (int w = 0; w < 3; w++)
                bv[w] = Bb4[((w * 2 + ks) * 4 + wn) * 32 + lane];
            #pragma unroll
            for (int mt = 0; mt < 2; mt++) {
                mma16(accU[mt][0], a[mt], bv[0].x, bv[0].y);
                mma16(accU[mt][1], a[mt], bv[0].z, bv[0].w);
                mma16(accR[mt][0], a[mt], bv[1].x, bv[1].y);
                mma16(accR[mt][1], a[mt], bv[1].z, bv[1].w);
                if (!ph) {
                    mma16(accX[mt][0], a[mt], bv[2].x, bv[2].y);
                    mma16(accX[mt][1], a[mt], bv[2].z, bv[2].w);
                } else {
                    mma16(accS[mt][0], a[mt], bv[2].x, bv[2].y);
                    mma16(accS[mt][1], a[mt], bv[2].z, bv[2].w);
                }
            }
        }
    }

    // ---- epilogue ----------------------------------------------------------
    #pragma unroll
    for (int mt = 0; mt < 2; mt++) {
        #pragma unroll
        for (int er = 0; er < 2; er++) {
            const int m = m0 + wm * 32 + mt * 16 + g + er * 8;
            const float am = __ldg(att + m);
            const float* hrow = hid + (size_t)m * 512;
            float*       orow = out + (size_t)m * 512;
            #pragma unroll
            for (int nt = 0; nt < 2; nt++) {
                const int col = n0 + wn * 16 + nt * 8 + t * 2;
                const float2 h2  = __ldg((const float2*)(hrow + col));
                const float2 bu2 = __ldg((const float2*)(b_u + col));
                const float2 br2 = __ldg((const float2*)(b_r + col));
                const float2 bh2 = __ldg((const float2*)(b_h + col));
                float o[2];
                #pragma unroll
                for (int ec = 0; ec < 2; ec++) {
                    const int e = er * 2 + ec;
                    const float zu = accU[mt][nt][e] + (ec ? bu2.y : bu2.x);
                    const float zr = accR[mt][nt][e] + (ec ? br2.y : br2.x);
                    const float u  = am * sigmoidf_fast(zu);
                    const float r  = sigmoidf_fast(zr);
                    const float hh = tanhf_fast(accX[mt][nt][e] +
                                                r * accS[mt][nt][e] +
                                                (ec ? bh2.y : bh2.x));
                    const float hv = ec ? h2.y : h2.x;
                    o[ec] = (1.0f - u) * hv + u * hh;
                }
                *(float2*)(orow + col) = make_float2(o[0], o[1]);
            }
        }
    }
}

extern "C" void kernel_launch(void* const* d_in, const int* in_sizes, int n_in,
                              void* d_out, int out_size) {
    (void)in_sizes; (void)n_in; (void)out_size;
    const float* x   = (const float*)d_in[0];
    const float* att = (const float*)d_in[1];
    const float* hid = (const float*)d_in[2];
    const float* Wu  = (const float*)d_in[3];
    const float* Uu  = (const float*)d_in[4];
    const float* b_u = (const float*)d_in[5];
    const float* Wr  = (const float*)d_in[6];
    const float* Ur  = (const float*)d_in[7];
    const float* b_r = (const float*)d_in[8];
    const float* Wh  = (const float*)d_in[9];
    const float* Uh  = (const float*)d_in[10];
    const float* b_h = (const float*)d_in[11];
    float* out = (float*)d_out;

    permA_kernel<<<dim3(4096, 2), 256>>>(x, hid);
    permB_kernel<<<dim3(128, 6), 256>>>(Wu, Wr, Wh, Uu, Ur, Uh);

    cudaFuncSetAttribute(augru_kernel,
                         cudaFuncAttributeMaxDynamicSharedMemorySize, SMEM_BYTES);
    dim3 grid(8, 128, 1);
    augru_kernel<<<grid, TB, SMEM_BYTES>>>(att, hid, b_u, b_r, b_h, out);
}

// round 11
// speedup vs baseline: 1.9001x; 1.0700x over previous
#include <cuda_runtime.h>
#include <cuda_fp16.h>
#include <cstdint>

// ---------------------------------------------------------------------------
// Fused AUGRU cell, mma.sync FP16 m16n8k16 (sm_100-target-safe PTX).
// Mainloop measured at the legacy tensor-pipe roofline (~800 FLOP/cyc/SM);
// this round trims overhead: coalesced staged permA + K64 chunks, 3 stages.
//   B=16384, D=H=512. CTA tile M=128 x N=64, 512 thr = 16 warps (4m x 4n).
//   Phase 0 (chunks 0-7):  A=x,  B={Wu,Wr,Wh} -> Zu,Zr,Zx
//   Phase 1 (chunks 8-15): A=h,  B={Uu,Ur,Uh} -> Zu,Zr,S
// A group (16B, 8 fp16) = m16n8k16 A-fragment of thread (g,t), see permA.
// B group (16B) = B-fragments for two n8 tiles, see permB.
// ---------------------------------------------------------------------------

#define TB 512

__device__ uint4 g_xa[1048576];   // x  fragment-permuted fp16 (16 MB)
__device__ uint4 g_ha[1048576];   // h  fragment-permuted fp16 (16 MB)
__device__ uint4 g_wb[196608];    // weights [ph][kc32][nb][w][ks][wn][lane] (3 MB)

#define A_BYTES    16384          // 1024 groups (128 rows x 64 K)
#define B_BYTES    24576          // 1536 groups (3 w x 64 rows x 64 K)
#define BUF_BYTES  40960
#define SMEM_BYTES (3 * BUF_BYTES)    // 122880

static __device__ __forceinline__ uint32_t smem_u32(const void* p) {
    uint32_t a;
    asm("{ .reg .u64 t; cvta.to.shared.u64 t, %1; cvt.u32.u64 %0, t; }"
        : "=r"(a) : "l"(p));
    return a;
}
static __device__ __forceinline__ void cp16(uint32_t dst, const void* src) {
    asm volatile("cp.async.cg.shared.global [%0], [%1], 16;"
                 :: "r"(dst), "l"(src) : "memory");
}
static __device__ __forceinline__ void cp_commit() {
    asm volatile("cp.async.commit_group;" ::: "memory");
}
static __device__ __forceinline__ uint32_t pack2(float lo, float hi) {
    uint32_t r;
    asm("cvt.rn.f16x2.f32 %0, %2, %1;" : "=r"(r) : "f"(lo), "f"(hi));
    return r;
}
static __device__ __forceinline__ void mma16(float* d, const uint32_t* a,
                                             uint32_t b0, uint32_t b1) {
    asm volatile(
        "mma.sync.aligned.m16n8k16.row.col.f32.f16.f16.f32 "
        "{%0,%1,%2,%3}, {%4,%5,%6,%7}, {%8,%9}, {%0,%1,%2,%3};"
        : "+f"(d[0]), "+f"(d[1]), "+f"(d[2]), "+f"(d[3])
        : "r"(a[0]), "r"(a[1]), "r"(a[2]), "r"(a[3]), "r"(b0), "r"(b1));
}
static __device__ __forceinline__ float sigmoidf_fast(float z) {
    return 1.0f / (1.0f + __expf(-z));
}
static __device__ __forceinline__ float tanhf_fast(float z) {
    return 1.0f - 2.0f / (1.0f + __expf(2.0f * z));
}

// ---- pre-pass A: staged transpose, fully coalesced both sides -------------
// grid (1024, 2) x 256. Block = 16 rows x 512 cols of x or hidden.
// Staging: pair-major uint32 st[c][r], c = k>>1 (0..255), pad 17.
__global__ void __launch_bounds__(256)
permA_kernel(const float* __restrict__ x, const float* __restrict__ hid)
{
    __shared__ uint32_t st[256 * 17];
    const int mB = blockIdx.x;
    const float* src = blockIdx.y ? hid : x;
    uint4*       dst = blockIdx.y ? g_ha : g_xa;
    const float4* s4 = reinterpret_cast<const float4*>(src + (size_t)mB * 16 * 512);

    // phase 1: coalesced read, pack fp16 pairs, staged store (2-way conflicts)
    #pragma unroll
    for (int it = 0; it < 8; it++) {
        const int idx = threadIdx.x + 256 * it;   // 0..2047
        const int r   = idx >> 7;                  // row 0..15
        const int c4  = idx & 127;                 // float4 col
        const float4 v = __ldg(s4 + r * 128 + c4);
        const int c = c4 * 2;                      // fp16-pair index
        st[c * 17 + r]       = pack2(v.x, v.y);
        st[(c + 1) * 17 + r] = pack2(v.z, v.w);
    }
    __syncthreads();

    // phase 2: gather fragment groups, coalesced uint4 store
    #pragma unroll
    for (int it = 0; it < 4; it++) {
        const int idx  = threadIdx.x + 256 * it;  // 0..1023
        const int lane = idx & 31;
        const int ks   = (idx >> 5) & 1;
        const int kc   = idx >> 6;
        const int g = lane >> 2, t = lane & 3;
        const int c = kc * 16 + ks * 8 + t;       // pair index of k = base+2t
        uint4 o;
        o.x = st[c * 17 + g];
        o.y = st[c * 17 + g + 8];
        o.z = st[(c + 4) * 17 + g];
        o.w = st[(c + 4) * 17 + g + 8];
        dst[(size_t)mB * 1024 + idx] = o;
    }
}

// ---- pre-pass B: grid (128, 6) x 256 (3 MB total, ~3us) --------------------
__global__ void __launch_bounds__(256)
permB_kernel(const float* __restrict__ Wu, const float* __restrict__ Wr,
             const float* __restrict__ Wh, const float* __restrict__ Uu,
             const float* __restrict__ Ur, const float* __restrict__ Uh)
{
    const int gi = blockIdx.x * 256 + threadIdx.x;       // 0..32767
    const int w  = blockIdx.y;
    const int ph = w / 3, w3 = w % 3;
    const float* ws[6] = {Wu, Wr, Wh, Uu, Ur, Uh};
    const float* src = ws[w];
    const int kc   = gi >> 11;
    const int rem  = gi & 2047;
    const int nb   = rem >> 8;
    const int rem2 = rem & 255;
    const int ks   = rem2 >> 7;
    const int wn   = (rem2 >> 5) & 3;
    const int lane = rem2 & 31;
    const int g = lane >> 2, t = lane & 3;
    const int k = kc * 32 + ks * 16 + 2 * t;
    const int n = nb * 64 + wn * 16 + g;
    const float* pk = src + (size_t)k * 512 + n;
    uint4 o;
    o.x = pack2(__ldg(pk),               __ldg(pk + 512));
    o.y = pack2(__ldg(pk + 8 * 512),     __ldg(pk + 9 * 512));
    o.z = pack2(__ldg(pk + 8),           __ldg(pk + 512 + 8));
    o.w = pack2(__ldg(pk + 8 * 512 + 8), __ldg(pk + 9 * 512 + 8));
    const size_t di = ((size_t)((((ph * 16 + kc) * 8 + nb) * 3 + w3) * 2 + ks)) * 128
                    + wn * 32 + lane;
    g_wb[di] = o;
}

// ---- main fused kernel ----------------------------------------------------
__global__ void __launch_bounds__(TB, 1)
augru_kernel(const float* __restrict__ att, const float* __restrict__ hid,
             const float* __restrict__ b_u, const float* __restrict__ b_r,
             const float* __restrict__ b_h, float* __restrict__ out)
{
    extern __shared__ char smc[];
    const uint32_t sb = smem_u32(smc);
    const int tid  = threadIdx.x;
    const int lane = tid & 31;
    const int wid  = tid >> 5;
    const int g = lane >> 2;
    const int t = lane & 3;
    const int wm = wid & 3;
    const int wn = wid >> 2;
    const int m0 = (int)blockIdx.y << 7;
    const int n0 = (int)blockIdx.x << 6;
    const int mB0 = m0 >> 4;
    const int nb  = n0 >> 6;

    float accU[2][2][4], accR[2][2][4], accX[2][2][4], accS[2][2][4];
    #pragma unroll
    for (int mt = 0; mt < 2; mt++)
        #pragma unroll
        for (int nt = 0; nt < 2; nt++)
            #pragma unroll
            for (int e = 0; e < 4; e++) {
                accU[mt][nt][e] = 0.f; accR[mt][nt][e] = 0.f;
                accX[mt][nt][e] = 0.f; accS[mt][nt][e] = 0.f;
            }

    // chunk = 64 K-columns. 16 chunks total (8 per phase).
    auto load_chunk = [&](int c, int b) {
        const int ph = (c >= 8);
        const int cc = c & 7;
        const uint32_t bo = sb + (uint32_t)b * BUF_BYTES;
        // A: 1024 groups, 2 per thread; src contiguous per mb.
        const uint4* Ag = ph ? g_ha : g_xa;
        #pragma unroll
        for (int i = 0; i < 2; i++) {
            const int j   = tid + TB * i;      // 0..1023
            const int mb  = j >> 7;
            const int low = j & 127;           // khalf*64 + ks2*32 + lane
            cp16(bo + j * 16,
                 Ag + ((size_t)(mB0 + mb) * 1024 + cc * 128 + low));
        }
        // B: 1536 groups = two kc32-blocks of 768 (source stride 6144).
        const uint4* Bsrc = g_wb + ((size_t)((ph * 16 + 2 * cc) * 8 + nb)) * 768;
        #pragma unroll
        for (int i = 0; i < 3; i++) {
            const int j = tid + TB * i;        // 0..1535
            const int khalf = (j >= 768);
            const int rem   = j - khalf * 768;
            cp16(bo + A_BYTES + j * 16, Bsrc + (size_t)khalf * 6144 + rem);
        }
        cp_commit();
    };

    load_chunk(0, 0);
    load_chunk(1, 1);

    for (int c = 0; c < 16; c++) {
        const int b = c % 3;
        if (c == 15) asm volatile("cp.async.wait_group 0;" ::: "memory");
        else         asm volatile("cp.async.wait_group 1;" ::: "memory");
        __syncthreads();
        if (c + 2 < 16) load_chunk(c + 2, (c + 2) % 3);

        const uint4* Ab4 = reinterpret_cast<const uint4*>(smc + b * BUF_BYTES);
        const uint4* Bb4 = reinterpret_cast<const uint4*>(smc + b * BUF_BYTES + A_BYTES);
        const int ph = (c >= 8);

        #pragma unroll
        for (int ks = 0; ks < 4; ks++) {
            const int khalf = ks >> 1, ks2 = ks & 1;
            uint32_t a[2][4];
            #pragma unroll
            for (int mt = 0; mt < 2; mt++) {
                const int mb = wm * 2 + mt;
                const uint4 av = Ab4[mb * 128 + khalf * 64 + ks2 * 32 + lane];
                a[mt][0] = av.x; a[mt][1] = av.y; a[mt][2] = av.z; a[mt][3] = av.w;
            }
            uint4 bv[3];
            #pragma unroll
            for (int w = 0; w < 3; w++)
                bv[w] = Bb4[khalf * 768 + ((w * 2 + ks2) * 4 + wn) * 32 + lane];
            #pragma unroll
            for (int mt = 0; mt < 2; mt++) {
                mma16(accU[mt][0], a[mt], bv[0].x, bv[0].y);
                mma16(accU[mt][1], a[mt], bv[0].z, bv[0].w);
                mma16(accR[mt][0], a[mt], bv[1].x, bv[1].y);
                mma16(accR[mt][1], a[mt], bv[1].z, bv[1].w);
                if (!ph) {
                    mma16(accX[mt][0], a[mt], bv[2].x, bv[2].y);
                    mma16(accX[mt][1], a[mt], bv[2].z, bv[2].w);
                } else {
                    mma16(accS[mt][0], a[mt], bv[2].x, bv[2].y);
                    mma16(accS[mt][1], a[mt], bv[2].z, bv[2].w);
                }
            }
        }
    }

    // ---- epilogue ----------------------------------------------------------
    #pragma unroll
    for (int mt = 0; mt < 2; mt++) {
        #pragma unroll
        for (int er = 0; er < 2; er++) {
            const int m = m0 + wm * 32 + mt * 16 + g + er * 8;
            const float am = __ldg(att + m);
            const float* hrow = hid + (size_t)m * 512;
            float*       orow = out + (size_t)m * 512;
            #pragma unroll
            for (int nt = 0; nt < 2; nt++) {
                const int col = n0 + wn * 16 + nt * 8 + t * 2;
                const float2 h2  = __ldg((const float2*)(hrow + col));
                const float2 bu2 = __ldg((const float2*)(b_u + col));
                const float2 br2 = __ldg((const float2*)(b_r + col));
                const float2 bh2 = __ldg((const float2*)(b_h + col));
                float o[2];
                #pragma unroll
                for (int ec = 0; ec < 2; ec++) {
                    const int e = er * 2 + ec;
                    const float zu = accU[mt][nt][e] + (ec ? bu2.y : bu2.x);
                    const float zr = accR[mt][nt][e] + (ec ? br2.y : br2.x);
                    const float u  = am * sigmoidf_fast(zu);
                    const float r  = sigmoidf_fast(zr);
                    const float hh = tanhf_fast(accX[mt][nt][e] +
                                                r * accS[mt][nt][e] +
                                                (ec ? bh2.y : bh2.x));
                    const float hv = ec ? h2.y : h2.x;
                    o[ec] = (1.0f - u) * hv + u * hh;
                }
                *(float2*)(orow + col) = make_float2(o[0], o[1]);
            }
        }
    }
}

extern "C" void kernel_launch(void* const* d_in, const int* in_sizes, int n_in,
                              void* d_out, int out_size) {
    (void)in_sizes; (void)n_in; (void)out_size;
    const float* x   = (const float*)d_in[0];
    const float* att = (const float*)d_in[1];
    const float* hid = (const float*)d_in[2];
    const float* Wu  = (const float*)d_in[3];
    const float* Uu  = (const float*)d_in[4];
    const float* b_u = (const float*)d_in[5];
    const float* Wr  = (const float*)d_in[6];
    const float* Ur  = (const float*)d_in[7];
    const float* b_r = (const float*)d_in[8];
    const float* Wh  = (const float*)d_in[9];
    const float* Uh  = (const float*)d_in[10];
    const float* b_h = (const float*)d_in[11];
    float* out = (float*)d_out;

    permA_kernel<<<dim3(1024, 2), 256>>>(x, hid);
    permB_kernel<<<dim3(128, 6), 256>>>(Wu, Wr, Wh, Uu, Ur, Uh);

    cudaFuncSetAttribute(augru_kernel,
                         cudaFuncAttributeMaxDynamicSharedMemorySize, SMEM_BYTES);
    dim3 grid(8, 128, 1);
    augru_kernel<<<grid, TB, SMEM_BYTES>>>(att, hid, b_u, b_r, b_h, out);
}